// round 1
// baseline (speedup 1.0000x reference)
#include <cuda_runtime.h>

#define PI_D 3.14159265358979323846

// ---------------- device globals (scratch + tables; no runtime allocs) ---------------
static __device__ float2 g_tw[512];     // exp(-2*pi*i*k/512)
static __device__ float2 g_post[512];   // DCT-II ortho post factors (c1, c2)
static __device__ float  g_tmp[67108864];   // 256 MB intermediate (8*32*512*512)

// ---------------- complex helpers ----------------
__device__ __forceinline__ float2 cadd(float2 a, float2 b){ return make_float2(a.x+b.x, a.y+b.y); }
__device__ __forceinline__ float2 csub(float2 a, float2 b){ return make_float2(a.x-b.x, a.y-b.y); }
__device__ __forceinline__ float2 cmul(float2 a, float2 b){
    return make_float2(a.x*b.x - a.y*b.y, a.x*b.y + a.y*b.x);
}
__device__ __forceinline__ float2 mul_mi(float2 a){ return make_float2(a.y, -a.x); } // * (-i)

// natural-order 8-point DFT (DIF), in place
__device__ __forceinline__ void dft8(float2 v[8]){
    const float K = 0.70710678118654752440f;
    float2 t0=cadd(v[0],v[4]), t1=cadd(v[1],v[5]), t2=cadd(v[2],v[6]), t3=cadd(v[3],v[7]);
    float2 u0=csub(v[0],v[4]);
    float2 s1=csub(v[1],v[5]);
    float2 u1=make_float2(K*(s1.x+s1.y), K*(s1.y-s1.x));      // * (K,-K)
    float2 u2=mul_mi(csub(v[2],v[6]));                        // * (0,-1)
    float2 s3=csub(v[3],v[7]);
    float2 u3=make_float2(K*(s3.y-s3.x), -K*(s3.x+s3.y));     // * (-K,-K)
    float2 d0=cadd(t0,t2), d1=cadd(t1,t3), d2=csub(t0,t2), d3=mul_mi(csub(t1,t3));
    v[0]=cadd(d0,d1); v[4]=csub(d0,d1); v[2]=cadd(d2,d3); v[6]=csub(d2,d3);
    float2 e0=cadd(u0,u2), e1=cadd(u1,u3), e2=csub(u0,u2), e3=mul_mi(csub(u1,u3));
    v[1]=cadd(e0,e1); v[5]=csub(e0,e1); v[3]=cadd(e2,e3); v[7]=csub(e2,e3);
}

// padded shared index: breaks power-of-2 bank patterns; max 511 -> 574 (< 576)
__device__ __forceinline__ int padi(int i){ return i + (i >> 3); }

// Stockham radix-8 512-pt FFT. Permuted REAL input already resides at re[padi(idx)].
// 64 threads per sequence (each block may host several sequences in disjoint re/im slices).
// On return: v[m] = Z[j + 64*m] (natural order). Contains __syncthreads (all threads call).
__device__ __forceinline__ void fft512_shared(float* re, float* im, int j, float2 v[8]){
    // ---- stage 1 (Ns=1, twiddle = 1): read real input
    #pragma unroll
    for (int r=0;r<8;r++) v[r] = make_float2(re[padi(j + (r<<6))], 0.f);
    dft8(v);
    __syncthreads();
    #pragma unroll
    for (int r=0;r<8;r++){ int d=(j<<3)+r; re[padi(d)]=v[r].x; im[padi(d)]=v[r].y; }
    __syncthreads();
    // ---- stage 2 (Ns=8)
    #pragma unroll
    for (int r=0;r<8;r++){ int s=padi(j+(r<<6)); v[r]=make_float2(re[s], im[s]); }
    {
        int jm = j & 7;
        #pragma unroll
        for (int r=1;r<8;r++) v[r] = cmul(v[r], g_tw[(r*jm)<<3]);
    }
    dft8(v);
    __syncthreads();
    {
        int b2 = ((j>>3)<<6) + (j&7);
        #pragma unroll
        for (int r=0;r<8;r++){ int d=b2+(r<<3); re[padi(d)]=v[r].x; im[padi(d)]=v[r].y; }
    }
    __syncthreads();
    // ---- stage 3 (Ns=64): output lands in natural order across v[]
    #pragma unroll
    for (int r=0;r<8;r++){ int s=padi(j+(r<<6)); v[r]=make_float2(re[s], im[s]); }
    #pragma unroll
    for (int r=1;r<8;r++) v[r] = cmul(v[r], g_tw[r*j]);
    dft8(v);
}

// ---------------- table init (runs inside the graph every launch; deterministic) -----
__global__ void init_tables(){
    int k = threadIdx.x;
    if (k < 512){
        double ang = -2.0 * PI_D * (double)k / 512.0;
        g_tw[k] = make_float2((float)cos(ang), (float)sin(ang));
        double th = PI_D * (double)k / 1024.0;              // pi*k/(2N), N=512
        double s2 = (k==0) ? (1.0/sqrt(512.0)) : (1.0/16.0); // 2*ortho scale
        g_post[k] = make_float2((float)(s2*cos(th)), (float)(s2*sin(th)));
    }
}

// ---------------- pass 1: DCT-II along W (contiguous rows) --------------------------
// 256 threads = 4 rows/block, 64 threads per row.
__global__ void __launch_bounds__(256) dct_pass1(const float* __restrict__ x){
    __shared__ float sre[4*576];
    __shared__ float sim[4*576];
    int tid = threadIdx.x;
    size_t base = (size_t)blockIdx.x * 2048;   // 4 rows * 512

    // fully-coalesced staged load, store Makhoul-permuted
    #pragma unroll
    for (int it=0; it<8; it++){
        int e  = tid + (it<<8);                // 0..2047
        int rl = e >> 9, pos = e & 511;
        int idx = (pos & 1) ? (511 - (pos>>1)) : (pos>>1);
        sre[rl*576 + padi(idx)] = x[base + e];
    }
    __syncthreads();

    int j = tid & 63, rl = tid >> 6;
    float2 v[8];
    fft512_shared(sre + rl*576, sim + rl*576, j, v);

    float* yr = g_tmp + base + ((size_t)rl << 9);
    #pragma unroll
    for (int r=0;r<8;r++){
        int k = j + (r<<6);
        float2 p = g_post[k];
        yr[k] = v[r].x*p.x + v[r].y*p.y;       // coalesced (j consecutive)
    }
}

// ---------------- pass 2: DCT-II along H (strided) ----------------------------------
// 512 threads = 8 columns/block, 64 threads per column. grid = (64, 256).
__global__ void __launch_bounds__(512) dct_pass2(float* __restrict__ out){
    __shared__ float sre[8*577];   // also aliased as output staging buffer
    __shared__ float sim[8*577];
    int tid = threadIdx.x;
    size_t ibase = (size_t)blockIdx.y * 262144 + ((size_t)blockIdx.x << 3);

    // load 512(H) x 8(W) tile, 32B-sector coalesced; store permuted per column
    #pragma unroll
    for (int it=0; it<8; it++){
        int e = tid + (it<<9);                 // 0..4095
        int h = e >> 3, c = e & 7;
        int idx = (h & 1) ? (511 - (h>>1)) : (h>>1);
        sre[c*577 + padi(idx)] = g_tmp[ibase + ((size_t)h<<9) + c];
    }
    __syncthreads();

    int j = tid & 63, c = tid >> 6;
    float2 v[8];
    fft512_shared(sre + c*577, sim + c*577, j, v);
    __syncthreads();               // all stage-3 reads done before aliasing sre

    // DCT post + stage to shared for coalesced global write
    #pragma unroll
    for (int r=0;r<8;r++){
        int k = j + (r<<6);
        float2 p = g_post[k];
        sre[k*9 + c] = v[r].x*p.x + v[r].y*p.y;   // max 4606 < 4616
    }
    __syncthreads();

    #pragma unroll
    for (int it=0; it<8; it++){
        int e = tid + (it<<9);
        int h = e >> 3, c2 = e & 7;
        out[ibase + ((size_t)h<<9) + c2] = sre[h*9 + c2];
    }
}

// ---------------- launch ------------------------------------------------------------
extern "C" void kernel_launch(void* const* d_in, const int* in_sizes, int n_in,
                              void* d_out, int out_size){
    const float* x = (const float*)d_in[0];
    float* out = (float*)d_out;

    init_tables<<<1, 512>>>();
    dct_pass1<<<32768, 256>>>(x);          // 131072 rows / 4 per block
    dim3 g2(64, 256);                      // 512/8 column-groups x 256 images
    dct_pass2<<<g2, 512>>>(out);
    (void)in_sizes; (void)n_in; (void)out_size;
}